// round 12
// baseline (speedup 1.0000x reference)
#include <cuda_runtime.h>
#include <cfloat>

#define T_DIM 2048
#define R_DIM 256
#define BS_DIM 32
#define IDX(t) ((t) + ((t) >> 5))   // smem skew: 1 pad float per 32
#define CSK 2112                    // skewed column size: 2048 + 64

// per-min-block minima (512 entries, fully overwritten each call)
__device__ float g_blockmin[512];

// ---------------- K_min: global min pass (reversed, L2-warms low bs) + out zero ----------------
__global__ void __launch_bounds__(256) min_kernel(const float* __restrict__ x,
                                                  const float* __restrict__ y,
                                                  float* __restrict__ out) {
    __shared__ float wmin[8];
    const int tid = threadIdx.x;
    const int bid = blockIdx.x;
    if (bid == 0 && tid < 4) out[tid] = 0.0f;

    const int idx = 511 - bid;                      // descending: bs0 read last
    const float* base = (idx & 1) ? y : x;
    const float4* p = (const float4*)base + (size_t)(idx >> 1) * 16384;  // 256 KB chunk
    float mn = FLT_MAX;
    #pragma unroll 8
    for (int k = 0; k < 64; k++) {
        float4 v = p[k * 256 + tid];
        mn = fminf(mn, fminf(fminf(v.x, v.y), fminf(v.z, v.w)));
    }
    for (int o = 16; o; o >>= 1) mn = fminf(mn, __shfl_xor_sync(0xffffffffu, mn, o));
    if ((tid & 31) == 0) wmin[tid >> 5] = mn;
    __syncthreads();
    if (tid == 0) {
        float m = wmin[0];
        #pragma unroll
        for (int i = 1; i < 8; i++) m = fminf(m, wmin[i]);
        g_blockmin[bid] = m;
    }
}

// ---------------- K_fused: direct strided load + in-smem cumsum + normalize + merge ----------------
// grid 4096: [bs(32)][rpair(128)], adjacent bids = adjacent r -> sector sharing via L2.
// Columns: c = p*2 + a  (c0=x/p0, c1=y/p0, c2=x/p1, c3=y/p1).
__global__ void __launch_bounds__(256, 5) fused_kernel(const float* __restrict__ x,
                                                       const float* __restrict__ y,
                                                       float* __restrict__ out) {
    __shared__ float sm[4 * CSK + 32];
    __shared__ float psum[4][128];      // per-column 128 segment sums -> exclusive offsets
    __shared__ float cinv[4];
    __shared__ float csinv[4];
    __shared__ float wmin[8];
    __shared__ float warr[8];

    const int tid = threadIdx.x;
    const int bs  = blockIdx.x >> 7;
    const int r0  = (blockIdx.x & 127) * 2;

    // ---- phase 0: global min from g_blockmin (512, L2-resident) ----
    {
        float m = fminf(g_blockmin[tid], g_blockmin[tid + 256]);
        for (int o = 16; o; o >>= 1) m = fminf(m, __shfl_xor_sync(0xffffffffu, m, o));
        if ((tid & 31) == 0) wmin[tid >> 5] = m;
    }

    // ---- phase 1: strided load + per-segment (16 t) cumsum into smem ----
    {
        const int a = tid >> 7;          // 0=x, 1=y
        const int u = tid & 127;         // segment id (16 t each)
        const float* src = (a ? y : x) + (size_t)bs * T_DIM * R_DIM + r0;
        float* colA = sm + a * CSK;          // p0
        float* colB = sm + (2 + a) * CSK;    // p1
        float runx = 0.0f, runy = 0.0f;
        const int t0 = u * 16;
        #pragma unroll
        for (int i = 0; i < 16; i++) {
            int t = t0 + i;
            float2 v = *(const float2*)(src + (size_t)t * R_DIM);
            runx += v.x; colA[IDX(t)] = runx;
            runy += v.y; colB[IDX(t)] = runy;
        }
        psum[a][u]     = runx;
        psum[2 + a][u] = runy;
    }
    __syncthreads();

    // shift from block-wide min reduction
    float mnv = wmin[0];
    #pragma unroll
    for (int i = 1; i < 8; i++) mnv = fminf(mnv, wmin[i]);
    const float shift = (mnv < 0.0f) ? (-1.1f * mnv) : 0.0f;

    // ---- phase 2: scan 128 segment sums per column (warp per column) ----
    if (tid < 128) {
        const int c = tid >> 5, l = tid & 31;
        float v0 = psum[c][l * 4 + 0];
        float v1 = psum[c][l * 4 + 1];
        float v2 = psum[c][l * 4 + 2];
        float v3 = psum[c][l * 4 + 3];
        float s0 = v0, s01 = s0 + v1, s012 = s01 + v2;
        float tot4 = s012 + v3;
        float sc = tot4;
        #pragma unroll
        for (int o = 1; o < 32; o <<= 1) {
            float t = __shfl_up_sync(0xffffffffu, sc, o);
            if (l >= o) sc += t;
        }
        float excl  = sc - tot4;
        float total = __shfl_sync(0xffffffffu, sc, 31);
        psum[c][l * 4 + 0] = excl;
        psum[c][l * 4 + 1] = excl + s0;
        psum[c][l * 4 + 2] = excl + s01;
        psum[c][l * 4 + 3] = excl + s012;
        if (l == 31) {
            float inv = 1.0f / (total + 2048.0f * shift);
            cinv[c]  = inv;
            csinv[c] = shift * inv;
        }
    }
    __syncthreads();

    // ---- phase 3: normalize in place: cdf = cum*inv + (off*inv + (t+1)*shift*inv) ----
    {
        const int a = tid >> 7;
        const int u = tid & 127;
        const int t0 = u * 16;
        #pragma unroll
        for (int cc = 0; cc < 2; cc++) {
            const int c = cc * 2 + a;
            float* col = sm + c * CSK;
            const float inv = cinv[c];
            const float si  = csinv[c];
            float base = fmaf((float)(t0 + 1), si, psum[c][u] * inv);
            #pragma unroll
            for (int i = 0; i < 16; i++) {
                int t = t0 + i;
                col[IDX(t)] = fmaf(col[IDX(t)], inv, base);
                base += si;
            }
        }
    }
    __syncthreads();

    // ---- phase 4: merge-path W2 (128 threads per problem, 32 endpoints each) ----
    const int p = tid >> 7;
    const int l = tid & 127;
    const int k0 = l * 32;
    const float* A = sm + (p * 2 + 0) * CSK;
    const float* B = sm + (p * 2 + 1) * CSK;

    int lo = (k0 > T_DIM) ? (k0 - T_DIM) : 0;
    int hi = (k0 < T_DIM) ? k0 : T_DIM;
    while (lo < hi) {
        int mid = (lo + hi) >> 1;
        if (A[IDX(mid)] <= B[IDX(k0 - 1 - mid)]) lo = mid + 1;
        else hi = mid;
    }
    int i = lo;
    int j = k0 - lo;

    float prevA = i ? A[IDX(i - 1)] : 0.0f;
    float prevB = j ? B[IDX(j - 1)] : 0.0f;
    float prev0 = fmaxf(prevA, prevB);
    float aq = (i < T_DIM) ? A[IDX(i)] : FLT_MAX;
    float bq = (j < T_DIM) ? B[IDX(j)] : FLT_MAX;
    float acc = 0.0f;

    if ((tid & 64) == 0) {
        // LEAN (ranks <= 2047): Abel form + exact per-chunk boundary terms.
        float fd0 = (float)(i - j);
        float fd2 = fd0 + fd0;
        acc = -prev0 * (fd0 * fd0);
        float lastq = prev0;
        #pragma unroll 8
        for (int s = 0; s < 32; s++) {
            bool takeA = (aq <= bq);
            float q = fminf(aq, bq);
            float sd = takeA ? -1.0f : 1.0f;
            float w = fmaf(sd, fd2, -1.0f);
            acc = fmaf(q, w, acc);
            fd2 = fmaf(-2.0f, sd, fd2);
            lastq = q;
            if (takeA) { i++; aq = A[IDX(i)]; }
            else       { j++; bq = B[IDX(j)]; }
        }
        float fdN = fd2 * 0.5f;
        acc = fmaf(lastq, fdN * fdN, acc);
    } else {
        // CLAMPED (ranks >= 2048)
        float prev = prev0;
        #pragma unroll 8
        for (int s = 0; s < 32; s++) {
            bool takeA = (aq <= bq);
            float q = fminf(aq, bq);
            int ic = (i < 2047) ? i : 2047;
            int jc = (j < 2047) ? j : 2047;
            float diff = (float)(ic - jc);
            acc += (q - prev) * (diff * diff);
            prev = q;
            if (takeA) { i++; aq = (i < T_DIM) ? A[IDX(i)] : FLT_MAX; }
            else       { j++; bq = (j < T_DIM) ? B[IDX(j)] : FLT_MAX; }
        }
    }
    acc *= (1.0f / 2048.0f) * (1.0f / 2048.0f);

    for (int o = 16; o; o >>= 1) acc += __shfl_xor_sync(0xffffffffu, acc, o);
    if ((tid & 31) == 0) warr[tid >> 5] = acc;
    __syncthreads();
    if (tid == 0) {
        float s = 0.0f;
        #pragma unroll
        for (int i2 = 0; i2 < 8; i2++) s += warr[i2];
        atomicAdd(&out[bs >> 3], s);
    }
}

extern "C" void kernel_launch(void* const* d_in, const int* in_sizes, int n_in,
                              void* d_out, int out_size) {
    const float* x = (const float*)d_in[0];
    const float* y = (const float*)d_in[1];
    float* out = (float*)d_out;

    min_kernel<<<512, 256>>>(x, y, out);
    fused_kernel<<<4096, 256>>>(x, y, out);
}

// round 14
// speedup vs baseline: 1.4608x; 1.4608x over previous
#include <cuda_runtime.h>
#include <cuda_fp16.h>
#include <cfloat>

#define T_DIM 2048
#define R_DIM 256
#define BS_DIM 32
#define IDX(t) ((t) + ((t) >> 5))   // smem skew: 1 pad float per 32
#define CSK 2112                    // skewed column size: 2048 + 64

// 64 MB transposed CDF scratch in HALF (within-segment cumsums): [array][bs][r][t]
__device__ __half g_cdf[2][BS_DIM][R_DIM][T_DIM];
// per-segment totals fp32 (segments of 128 t): [array][bs][r][seg16]
__device__ float g_segtot[2][BS_DIM][R_DIM][16];
// per-block minima from cdf_kernel (1024 blocks, fully overwritten each call)
__device__ float g_blockmin[1024];

// ---------------- Kernel A: transpose + SEGMENT-LOCAL cumsum (fp16 out) + min ----------------
// grid 1024: [array(2)][bs(32)][rtile(8)][thalf(2)], 256 threads.
// Warp = 128-t segment; lane = r within 32-wide r tile. Cumsum RESETS per 128-t segment.
__global__ void __launch_bounds__(256) cdf_kernel(const float* __restrict__ x,
                                                  const float* __restrict__ y,
                                                  float* __restrict__ out) {
    __shared__ float tile[8][32][33];
    __shared__ float wmin[8];

    const int bid = blockIdx.x;
    const int a    = bid >> 9;
    const int rem  = bid & 511;
    const int bs   = rem >> 4;
    const int rem2 = rem & 15;
    const int r0   = (rem2 >> 1) * 32;
    const int tb   = (rem2 & 1) * 1024;

    if (bid == 0 && threadIdx.x < 4) out[threadIdx.x] = 0.0f;

    const int lane = threadIdx.x & 31;   // r'
    const int seg  = threadIdx.x >> 5;   // warp id -> 128-t segment

    const float* src = (a ? y : x) + (size_t)bs * T_DIM * R_DIM + r0 + lane;

    float run = 0.0f;                    // within-segment running sum (fp32)
    float mn = FLT_MAX;

    const int row = lane >> 2;   // 0..7
    const int c4  = lane & 3;    // 0..3 (8-t group)

    float (*t33)[33] = tile[seg];        // this warp's 32x33 slice

    #pragma unroll 1
    for (int ch = 0; ch < 4; ch++) {
        const int t0 = tb + seg * 128 + ch * 32;
        #pragma unroll
        for (int h = 0; h < 2; h++) {
            float v[16];
            #pragma unroll
            for (int i = 0; i < 16; i++)
                v[i] = src[(size_t)(t0 + h * 16 + i) * R_DIM];
            #pragma unroll
            for (int i = 0; i < 16; i++) {
                mn = fminf(mn, v[i]);
                run += v[i];
                t33[lane][h * 16 + i] = run;   // tile holds SEGMENT cumsum
            }
        }
        __syncwarp();
        // drain transposed as half2: conflict-free scalar LDS, STG.128 (8 halves)
        #pragma unroll
        for (int rb = 0; rb < 4; rb++) {
            int rr = rb * 8 + row;
            union { __half2 h[4]; uint4 u; } pk;
            #pragma unroll
            for (int k = 0; k < 4; k++)
                pk.h[k] = __floats2half2_rn(t33[rr][c4 * 8 + 2 * k],
                                            t33[rr][c4 * 8 + 2 * k + 1]);
            *(uint4*)&g_cdf[a][bs][r0 + rr][t0 + c4 * 8] = pk.u;
        }
        __syncwarp();
    }
    // run = per-lane cumsum over this 128-t segment (4 chunks of 32)
    g_segtot[a][bs][r0 + lane][(tb >> 7) + seg] = run;

    // block min reduce -> g_blockmin[bid]
    for (int o = 16; o; o >>= 1) mn = fminf(mn, __shfl_xor_sync(0xffffffffu, mn, o));
    if (lane == 0) wmin[seg] = mn;
    __syncthreads();
    if (threadIdx.x == 0) {
        float m = wmin[0];
        #pragma unroll
        for (int i = 1; i < 8; i++) m = fminf(m, wmin[i]);
        g_blockmin[bid] = m;
    }
}

// ---------------- Kernel B: stage normalized CDFs (half in) + merge-path W2 ----------------
// grid 4096: [bs(32)][rpair(128)], 256 threads, 2 problems per block.
__global__ void __launch_bounds__(256) w2_kernel(float* __restrict__ out) {
    __shared__ float sm[4 * CSK + 32];   // +32 pad: final-iteration dead loads
    __shared__ float coffs[4][16];       // pre-scaled: off_seg * inv
    __shared__ float cinv[4];
    __shared__ float csinv[4];           // shift * inv
    __shared__ float redsm[8];
    __shared__ float warr[8];

    const int tid = threadIdx.x;
    const int bs  = blockIdx.x >> 7;
    const int r0  = (blockIdx.x & 127) * 2;

    // ---- global min from g_blockmin (1024 entries, L2-resident) ----
    {
        float m = fminf(fminf(g_blockmin[tid],       g_blockmin[tid + 256]),
                        fminf(g_blockmin[tid + 512], g_blockmin[tid + 768]));
        for (int o = 16; o; o >>= 1) m = fminf(m, __shfl_xor_sync(0xffffffffu, m, o));
        if ((tid & 31) == 0) redsm[tid >> 5] = m;
    }
    __syncthreads();
    float mnv = redsm[0];
    #pragma unroll
    for (int i = 1; i < 8; i++) mnv = fminf(mnv, redsm[i]);
    const float shift = (mnv < 0.0f) ? (-1.1f * mnv) : 0.0f;

    // per-column segment-offset prefix + normalization (pre-scaled by inv)
    if (tid < 4) {
        int c = tid, aa = c & 1, pp = c >> 1;
        const float* st = g_segtot[aa][bs][r0 + pp];
        float pref[16];
        float runp = 0.0f;
        #pragma unroll
        for (int s = 0; s < 16; s++) { pref[s] = runp; runp += st[s]; }
        float inv = 1.0f / (runp + 2048.0f * shift);
        cinv[c] = inv;
        csinv[c] = shift * inv;
        #pragma unroll
        for (int s = 0; s < 16; s++) coffs[c][s] = pref[s] * inv;
    }
    __syncthreads();

    // stage: LDG.128 = 8 halves, convert + FFMA normalize, scalar skewed smem stores
    {
        const int c = tid >> 6;
        const int l64 = tid & 63;
        const int aa = c & 1, pp = c >> 1;
        const uint4* srcc = (const uint4*)&g_cdf[aa][bs][r0 + pp][0];
        float* dst = sm + c * CSK;
        const float inv = cinv[c];
        const float si  = csinv[c];
        const float si2 = si + si;
        const float si4 = si2 + si2;
        #pragma unroll
        for (int it = 0; it < 4; it++) {
            int g = it * 64 + l64;          // 8-half group index
            uint4 u = srcc[g];
            int t = g * 8;
            // base = off*inv + (t+1)*shift*inv   (segment = t>>7, constant within group)
            float base = fmaf((float)(t + 1), si, coffs[c][t >> 7]);
            float2 f0 = __half22float2(*reinterpret_cast<__half2*>(&u.x));
            float2 f1 = __half22float2(*reinterpret_cast<__half2*>(&u.y));
            float2 f2 = __half22float2(*reinterpret_cast<__half2*>(&u.z));
            float2 f3 = __half22float2(*reinterpret_cast<__half2*>(&u.w));
            dst[IDX(t + 0)] = fmaf(f0.x, inv, base);
            dst[IDX(t + 1)] = fmaf(f0.y, inv, base + si);
            dst[IDX(t + 2)] = fmaf(f1.x, inv, base + si2);
            dst[IDX(t + 3)] = fmaf(f1.y, inv, base + si2 + si);
            float base4 = base + si4;
            dst[IDX(t + 4)] = fmaf(f2.x, inv, base4);
            dst[IDX(t + 5)] = fmaf(f2.y, inv, base4 + si);
            dst[IDX(t + 6)] = fmaf(f3.x, inv, base4 + si2);
            dst[IDX(t + 7)] = fmaf(f3.y, inv, base4 + si2 + si);
        }
    }
    __syncthreads();

    // ---- merge-path: 128 threads per problem, 32 merged endpoints each ----
    const int p = tid >> 7;          // problem 0..1
    const int l = tid & 127;         // chunk id
    const int k0 = l * 32;           // merged rank of first element
    const float* A = sm + (p * 2 + 0) * CSK;
    const float* B = sm + (p * 2 + 1) * CSK;

    int lo = (k0 > T_DIM) ? (k0 - T_DIM) : 0;
    int hi = (k0 < T_DIM) ? k0 : T_DIM;
    while (lo < hi) {
        int mid = (lo + hi) >> 1;
        if (A[IDX(mid)] <= B[IDX(k0 - 1 - mid)]) lo = mid + 1;
        else hi = mid;
    }
    int i = lo;
    int j = k0 - lo;

    float prevA = i ? A[IDX(i - 1)] : 0.0f;
    float prevB = j ? B[IDX(j - 1)] : 0.0f;
    float prev0 = fmaxf(prevA, prevB);
    float aq = (i < T_DIM) ? A[IDX(i)] : FLT_MAX;
    float bq = (j < T_DIM) ? B[IDX(j)] : FLT_MAX;
    float acc = 0.0f;

    if ((tid & 64) == 0) {
        // LEAN (ranks <= 2047): Abel form + exact per-chunk boundary terms.
        float fd0 = (float)(i - j);
        float fd2 = fd0 + fd0;
        acc = -prev0 * (fd0 * fd0);
        float lastq = prev0;
        #pragma unroll 8
        for (int s = 0; s < 32; s++) {
            bool takeA = (aq <= bq);
            float q = fminf(aq, bq);
            float sd = takeA ? -1.0f : 1.0f;
            float w = fmaf(sd, fd2, -1.0f);
            acc = fmaf(q, w, acc);
            fd2 = fmaf(-2.0f, sd, fd2);
            lastq = q;
            if (takeA) { i++; aq = A[IDX(i)]; }
            else       { j++; bq = B[IDX(j)]; }
        }
        float fdN = fd2 * 0.5f;
        acc = fmaf(lastq, fdN * fdN, acc);
    } else {
        // CLAMPED (ranks >= 2048)
        float prev = prev0;
        #pragma unroll 8
        for (int s = 0; s < 32; s++) {
            bool takeA = (aq <= bq);
            float q = fminf(aq, bq);
            int ic = (i < 2047) ? i : 2047;
            int jc = (j < 2047) ? j : 2047;
            float diff = (float)(ic - jc);
            acc += (q - prev) * (diff * diff);
            prev = q;
            if (takeA) { i++; aq = (i < T_DIM) ? A[IDX(i)] : FLT_MAX; }
            else       { j++; bq = (j < T_DIM) ? B[IDX(j)] : FLT_MAX; }
        }
    }
    acc *= (1.0f / 2048.0f) * (1.0f / 2048.0f);

    for (int o = 16; o; o >>= 1) acc += __shfl_xor_sync(0xffffffffu, acc, o);
    if ((tid & 31) == 0) warr[tid >> 5] = acc;
    __syncthreads();
    if (tid == 0) {
        float s = 0.0f;
        #pragma unroll
        for (int i2 = 0; i2 < 8; i2++) s += warr[i2];
        atomicAdd(&out[bs >> 3], s);
    }
}

extern "C" void kernel_launch(void* const* d_in, const int* in_sizes, int n_in,
                              void* d_out, int out_size) {
    const float* x = (const float*)d_in[0];
    const float* y = (const float*)d_in[1];
    float* out = (float*)d_out;

    cdf_kernel<<<2 * BS_DIM * 16, 256>>>(x, y, out);
    w2_kernel<<<BS_DIM * (R_DIM / 2), 256>>>(out);
}